// round 6
// baseline (speedup 1.0000x reference)
#include <cuda_runtime.h>
#include <cuda_bf16.h>

// out[b,i,j] = softmax_j( exp( exp(-||x_bi - x_bj||^2 * p) ) ), B=128, K=1024.
//
// R6: R5 structure, but 8 rows/block to halve per-thread register state and
// fit 3 blocks/SM (occ 46% -> ~72%). R5 was latency-bound: all pipes <47%,
// 61 regs pinned by 32 v-values -> too little ILP to hide the dependent
// 2x EX2 (32 cyc MUFU chain).
//  - Block = (b, 8-row tile), 512 threads / 16 warps, grid 16384.
//  - Warp w owns 64 columns; lane holds c-points jb, jb+1 in registers.
//  - Row loop: broadcast LDS, 8 fma ops, 2x2 EX2, no shuffles.
//  - Post-loop butterfly: 3 halving stages + xor8 + xor16 = 9 SHFL/warp.
//  - v0[8]+v1[8] regs; __launch_bounds__(512,3) caps at 42 regs.

static constexpr int K = 1024;
static constexpr int THREADS = 512;
static constexpr int ROWS = 8;
static constexpr float LOG2E = 1.4426950408889634f;
static constexpr float LOG2_LOG2E = 0.5287663729448977f;  // log2(log2(e))

__device__ __forceinline__ float ex2f(float x) {
    float r;
    asm("ex2.approx.f32 %0, %1;" : "=f"(r) : "f"(x));
    return r;
}

__global__ void __launch_bounds__(THREADS, 3)
adjacency_softmax_kernel(const float* __restrict__ coords,
                         const float* __restrict__ prec,
                         float* __restrict__ out)
{
    __shared__ float4 pk[K];            // (x, y, z, ||x||^2 * q), q = -p*log2e
    __shared__ float  wsum[ROWS][17];   // per-warp full row sums (padded)
    __shared__ float  inv_s[ROWS];

    const int b    = blockIdx.x >> 7;
    const int row0 = (blockIdx.x & 127) << 3;
    const int tid  = threadIdx.x;

    const float p = prec[0];
    const float q = -p * LOG2E;

    const float* cb = coords + (size_t)b * K * 3;
    #pragma unroll
    for (int j = tid; j < K; j += THREADS) {
        float x = cb[j * 3 + 0];
        float y = cb[j * 3 + 1];
        float z = cb[j * 3 + 2];
        pk[j] = make_float4(x, y, z, (x * x + y * y + z * z) * q);
    }
    __syncthreads();

    const int wid  = tid >> 5;
    const int lane = tid & 31;
    const int jb   = (wid << 6) + (lane << 1);   // 2 consecutive columns/lane

    const float4 c0 = pk[jb + 0];       // column points: registers, loaded once
    const float4 c1 = pk[jb + 1];
    const float  s2  = -2.0f * q;       // +2*p*log2e
    const float  cw0 = c0.w + LOG2_LOG2E;
    const float  cw1 = c1.w + LOG2_LOG2E;

    float v0[ROWS], v1[ROWS];

    #pragma unroll
    for (int r = 0; r < ROWS; r++) {
        const float4 a = pk[row0 + r];              // broadcast LDS (once/row)

        float d0 = a.x * c0.x;
        float d1 = a.x * c1.x;
        d0 = fmaf(a.y, c0.y, d0);
        d1 = fmaf(a.y, c1.y, d1);
        d0 = fmaf(a.z, c0.z, d0);
        d1 = fmaf(a.z, c1.z, d1);

        const float arg0 = fmaf(d0, s2, a.w + cw0);
        const float arg1 = fmaf(d1, s2, a.w + cw1);

        v0[r] = ex2f(ex2f(arg0));                   // exp(exp(-d*p))
        v1[r] = ex2f(ex2f(arg1));
    }

    // ---- Deferred cross-lane reduction: array-halving butterfly ----
    float s[ROWS];
    #pragma unroll
    for (int r = 0; r < ROWS; r++) s[r] = v0[r] + v1[r];

    #pragma unroll
    for (int stage = 0; stage < 3; stage++) {
        const int m = 1 << stage;        // xor mask: 1, 2, 4
        const int h = 4 >> stage;        // surviving half-size: 4, 2, 1
        const bool up = (lane & m) != 0;
        #pragma unroll
        for (int r = 0; r < h; r++) {
            const float x = up ? s[r + h] : s[r];
            const float y = up ? s[r]     : s[r + h];
            s[r] = x + __shfl_xor_sync(0xFFFFFFFFu, y, m);
        }
    }
    {
        float t = s[0];
        t += __shfl_xor_sync(0xFFFFFFFFu, t, 8);
        t += __shfl_xor_sync(0xFFFFFFFFu, t, 16);
        if (lane < 8) {
            const int row = ((lane & 1) << 2) | (lane & 2) | ((lane & 4) >> 2);
            wsum[row][wid] = t;
        }
    }
    __syncthreads();

    if (tid < ROWS) {
        float acc = 0.0f;
        #pragma unroll
        for (int w = 0; w < 16; w++) acc += wsum[tid][w];
        inv_s[tid] = __fdividef(1.0f, acc);
    }
    __syncthreads();

    float* __restrict__ ob = out + ((size_t)b * K + row0) * K + jb;

    #pragma unroll
    for (int r = 0; r < ROWS; r++) {
        const float inv = inv_s[r];                 // broadcast LDS
        float2 res = make_float2(v0[r] * inv, v1[r] * inv);
        *reinterpret_cast<float2*>(ob + (size_t)r * K) = res;   // STG.64
    }
}

extern "C" void kernel_launch(void* const* d_in, const int* in_sizes, int n_in,
                              void* d_out, int out_size)
{
    const float* coords = (const float*)d_in[0];   // [128, 1024, 3] f32
    const float* prec   = (const float*)d_in[1];   // [1] f32
    float* out          = (float*)d_out;           // [128, 1024, 1024] f32

    dim3 grid(128 * (K / ROWS));   // 16384 blocks
    adjacency_softmax_kernel<<<grid, THREADS>>>(coords, prec, out);
}

// round 7
// speedup vs baseline: 1.0115x; 1.0115x over previous
#include <cuda_runtime.h>
#include <cuda_bf16.h>

// out[b,i,j] = softmax_j( exp( exp(-||x_bi - x_bj||^2 * p) ) ), B=128, K=1024.
//
// R7: minimize LSU cycles. STG issue cost is 5/7.75/12 cyc for .32/.64/.128
// (per SASS_QUICKREF), so 4 cols/lane + STG.128 cuts the store bill from
// ~62us (R5, STG.64) to ~48us and L1 pressure with it.
//  - Block = (b, 16-row tile), 512 threads, grid 8192 (no R6 staging tax).
//  - 16 warps = 2 groups of 8: group g handles rows row0+8g..+8g+7; warp
//    (wid&7) owns 128 columns; lane holds 4 CONSECUTIVE c-points in regs.
//  - Column points pre-scaled once: cs = s2*c, cw' = c.w + log2(log2e);
//    per element: acc = a.w + cw'; 3x fma(a, cs); EX2; EX2  (4 fma-class ops).
//  - Deferred butterfly reduction (9 SHFL/warp), bitrev3 row map.
//  - v[4][8] = 32 value regs; ~60 regs total; __launch_bounds__(512,2).

static constexpr int K = 1024;
static constexpr int THREADS = 512;
static constexpr int ROWS = 16;        // per block
static constexpr int RH = 8;           // rows per warp-group
static constexpr float LOG2E = 1.4426950408889634f;
static constexpr float LOG2_LOG2E = 0.5287663729448977f;  // log2(log2(e))

__device__ __forceinline__ float ex2f(float x) {
    float r;
    asm("ex2.approx.f32 %0, %1;" : "=f"(r) : "f"(x));
    return r;
}

__global__ void __launch_bounds__(THREADS, 2)
adjacency_softmax_kernel(const float* __restrict__ coords,
                         const float* __restrict__ prec,
                         float* __restrict__ out)
{
    __shared__ float4 pk[K];           // (x, y, z, ||x||^2 * q), q = -p*log2e
    __shared__ float  wsum[ROWS][8];   // per-warp full row sums
    __shared__ float  inv_s[ROWS];

    const int b    = blockIdx.x >> 6;
    const int row0 = (blockIdx.x & 63) << 4;
    const int tid  = threadIdx.x;

    const float p = prec[0];
    const float q = -p * LOG2E;

    const float* cb = coords + (size_t)b * K * 3;
    #pragma unroll
    for (int j = tid; j < K; j += THREADS) {
        float x = cb[j * 3 + 0];
        float y = cb[j * 3 + 1];
        float z = cb[j * 3 + 2];
        pk[j] = make_float4(x, y, z, (x * x + y * y + z * z) * q);
    }
    __syncthreads();

    const int wid  = tid >> 5;
    const int lane = tid & 31;
    const int grp  = wid >> 3;                  // 0 or 1: row half
    const int jb   = ((wid & 7) << 7) + (lane << 2);   // 4 consecutive cols
    const int rbase = row0 + grp * RH;

    const float s2 = -2.0f * q;                 // +2*p*log2e

    // Column points: load once, pre-scale so per-element work is 1 FADD+3 FMA.
    float4 c0 = pk[jb + 0];
    float4 c1 = pk[jb + 1];
    float4 c2 = pk[jb + 2];
    float4 c3 = pk[jb + 3];
    const float cw0 = c0.w + LOG2_LOG2E;
    const float cw1 = c1.w + LOG2_LOG2E;
    const float cw2 = c2.w + LOG2_LOG2E;
    const float cw3 = c3.w + LOG2_LOG2E;
    c0.x *= s2; c0.y *= s2; c0.z *= s2;
    c1.x *= s2; c1.y *= s2; c1.z *= s2;
    c2.x *= s2; c2.y *= s2; c2.z *= s2;
    c3.x *= s2; c3.y *= s2; c3.z *= s2;

    float v0[RH], v1[RH], v2[RH], v3[RH];

    #pragma unroll
    for (int r = 0; r < RH; r++) {
        const float4 a = pk[rbase + r];          // broadcast LDS (once/row)

        float t0 = a.w + cw0;
        float t1 = a.w + cw1;
        float t2 = a.w + cw2;
        float t3 = a.w + cw3;
        t0 = fmaf(a.x, c0.x, t0);
        t1 = fmaf(a.x, c1.x, t1);
        t2 = fmaf(a.x, c2.x, t2);
        t3 = fmaf(a.x, c3.x, t3);
        t0 = fmaf(a.y, c0.y, t0);
        t1 = fmaf(a.y, c1.y, t1);
        t2 = fmaf(a.y, c2.y, t2);
        t3 = fmaf(a.y, c3.y, t3);
        t0 = fmaf(a.z, c0.z, t0);
        t1 = fmaf(a.z, c1.z, t1);
        t2 = fmaf(a.z, c2.z, t2);
        t3 = fmaf(a.z, c3.z, t3);

        v0[r] = ex2f(ex2f(t0));                  // exp(exp(-d*p))
        v1[r] = ex2f(ex2f(t1));
        v2[r] = ex2f(ex2f(t2));
        v3[r] = ex2f(ex2f(t3));
    }

    // ---- Deferred cross-lane reduction: array-halving butterfly ----
    float s[RH];
    #pragma unroll
    for (int r = 0; r < RH; r++)
        s[r] = (v0[r] + v1[r]) + (v2[r] + v3[r]);

    #pragma unroll
    for (int stage = 0; stage < 3; stage++) {
        const int m = 1 << stage;        // xor mask: 1, 2, 4
        const int h = 4 >> stage;        // surviving half-size: 4, 2, 1
        const bool up = (lane & m) != 0;
        #pragma unroll
        for (int r = 0; r < h; r++) {
            const float x = up ? s[r + h] : s[r];
            const float y = up ? s[r]     : s[r + h];
            s[r] = x + __shfl_xor_sync(0xFFFFFFFFu, y, m);
        }
    }
    {
        float t = s[0];
        t += __shfl_xor_sync(0xFFFFFFFFu, t, 8);
        t += __shfl_xor_sync(0xFFFFFFFFu, t, 16);
        if (lane < 8) {
            const int row = ((lane & 1) << 2) | (lane & 2) | ((lane & 4) >> 2);
            wsum[grp * RH + row][wid & 7] = t;
        }
    }
    __syncthreads();

    if (tid < ROWS) {
        float acc = 0.0f;
        #pragma unroll
        for (int w = 0; w < 8; w++) acc += wsum[tid][w];
        inv_s[tid] = __fdividef(1.0f, acc);
    }
    __syncthreads();

    float* __restrict__ ob = out + ((size_t)b * K + rbase) * K + jb;

    #pragma unroll
    for (int r = 0; r < RH; r++) {
        const float inv = inv_s[grp * RH + r];   // broadcast LDS
        float4 res = make_float4(v0[r] * inv, v1[r] * inv,
                                 v2[r] * inv, v3[r] * inv);
        *reinterpret_cast<float4*>(ob + (size_t)r * K) = res;   // STG.128
    }
}

extern "C" void kernel_launch(void* const* d_in, const int* in_sizes, int n_in,
                              void* d_out, int out_size)
{
    const float* coords = (const float*)d_in[0];   // [128, 1024, 3] f32
    const float* prec   = (const float*)d_in[1];   // [1] f32
    float* out          = (float*)d_out;           // [128, 1024, 1024] f32

    dim3 grid(128 * (K / ROWS));   // 8192 blocks
    adjacency_softmax_kernel<<<grid, THREADS>>>(coords, prec, out);
}

// round 8
// speedup vs baseline: 1.2611x; 1.2468x over previous
#include <cuda_runtime.h>
#include <cuda_bf16.h>

// out[b,i,j] = softmax_j( exp( exp(-||x_bi - x_bj||^2 * p) ) ), B=128, K=1024.
//
// R8: delete all serialization except the one reduction barrier.
//  - NO smem staging, NO staging barrier, NO STS: column points read straight
//    from L2 (coords = 1.5MB, L2/L1-resident), row points via uniform LDG
//    broadcast + 5 FMA. R3-R7 all paid a 16KB stage + block sync first.
//  - 256 threads / 8 warps / 8 rows per block, 4 consecutive cols per lane
//    (STG.128), grid 16384. ~60 regs, tiny smem -> 4 independent blocks/SM
//    whose compute/store phases interleave -> smooth DRAM instead of bursts.
//  - Streaming stores __stcs: output written once, never re-read; keep it
//    from churning L2.
//  - Deferred butterfly reduction (9 SHFL/warp), one __syncthreads pair.

static constexpr int K = 1024;
static constexpr int THREADS = 256;
static constexpr int ROWS = 8;
static constexpr float LOG2E = 1.4426950408889634f;
static constexpr float LOG2_LOG2E = 0.5287663729448977f;  // log2(log2(e))

__device__ __forceinline__ float ex2f(float x) {
    float r;
    asm("ex2.approx.f32 %0, %1;" : "=f"(r) : "f"(x));
    return r;
}

__global__ void __launch_bounds__(THREADS, 4)
adjacency_softmax_kernel(const float* __restrict__ coords,
                         const float* __restrict__ prec,
                         float* __restrict__ out)
{
    __shared__ float wsum[ROWS][9];    // per-warp row sums (padded)
    __shared__ float inv_s[ROWS];

    const int b    = blockIdx.x >> 7;
    const int row0 = (blockIdx.x & 127) << 3;
    const int tid  = threadIdx.x;
    const int wid  = tid >> 5;
    const int lane = tid & 31;
    const int jb   = (wid << 7) + (lane << 2);   // 4 consecutive columns

    const float p  = prec[0];
    const float q  = -p * LOG2E;
    const float s2 = -2.0f * q;                  // +2*p*log2e

    const float* __restrict__ cb = coords + (size_t)b * K * 3;

    // ---- Column points: straight from L2, pre-scaled into registers ----
    float csx[4], csy[4], csz[4], cw[4];
    #pragma unroll
    for (int c = 0; c < 4; c++) {
        const float x = cb[(jb + c) * 3 + 0];
        const float y = cb[(jb + c) * 3 + 1];
        const float z = cb[(jb + c) * 3 + 2];
        cw[c]  = fmaf(x, x, fmaf(y, y, z * z)) * q + LOG2_LOG2E;
        csx[c] = x * s2;
        csy[c] = y * s2;
        csz[c] = z * s2;
    }

    float v0[ROWS], v1[ROWS], v2[ROWS], v3[ROWS];

    #pragma unroll
    for (int r = 0; r < ROWS; r++) {
        // Row point: uniform-address LDG (L1-hit broadcast after first touch).
        const float ax = cb[(row0 + r) * 3 + 0];
        const float ay = cb[(row0 + r) * 3 + 1];
        const float az = cb[(row0 + r) * 3 + 2];
        const float aw = fmaf(ax, ax, fmaf(ay, ay, az * az)) * q;

        float t0 = aw + cw[0];
        float t1 = aw + cw[1];
        float t2 = aw + cw[2];
        float t3 = aw + cw[3];
        t0 = fmaf(ax, csx[0], t0);
        t1 = fmaf(ax, csx[1], t1);
        t2 = fmaf(ax, csx[2], t2);
        t3 = fmaf(ax, csx[3], t3);
        t0 = fmaf(ay, csy[0], t0);
        t1 = fmaf(ay, csy[1], t1);
        t2 = fmaf(ay, csy[2], t2);
        t3 = fmaf(ay, csy[3], t3);
        t0 = fmaf(az, csz[0], t0);
        t1 = fmaf(az, csz[1], t1);
        t2 = fmaf(az, csz[2], t2);
        t3 = fmaf(az, csz[3], t3);

        v0[r] = ex2f(ex2f(t0));                  // exp(exp(-d*p))
        v1[r] = ex2f(ex2f(t1));
        v2[r] = ex2f(ex2f(t2));
        v3[r] = ex2f(ex2f(t3));
    }

    // ---- Deferred cross-lane reduction: array-halving butterfly ----
    float s[ROWS];
    #pragma unroll
    for (int r = 0; r < ROWS; r++)
        s[r] = (v0[r] + v1[r]) + (v2[r] + v3[r]);

    #pragma unroll
    for (int stage = 0; stage < 3; stage++) {
        const int m = 1 << stage;        // xor mask: 1, 2, 4
        const int h = 4 >> stage;        // surviving half-size: 4, 2, 1
        const bool up = (lane & m) != 0;
        #pragma unroll
        for (int r = 0; r < h; r++) {
            const float x = up ? s[r + h] : s[r];
            const float y = up ? s[r]     : s[r + h];
            s[r] = x + __shfl_xor_sync(0xFFFFFFFFu, y, m);
        }
    }
    {
        float t = s[0];
        t += __shfl_xor_sync(0xFFFFFFFFu, t, 8);
        t += __shfl_xor_sync(0xFFFFFFFFu, t, 16);
        if (lane < 8) {
            const int row = ((lane & 1) << 2) | (lane & 2) | ((lane & 4) >> 2);
            wsum[row][wid] = t;
        }
    }
    __syncthreads();

    if (tid < ROWS) {
        float acc = 0.0f;
        #pragma unroll
        for (int w = 0; w < 8; w++) acc += wsum[tid][w];
        inv_s[tid] = __fdividef(1.0f, acc);
    }
    __syncthreads();

    float* __restrict__ ob = out + ((size_t)b * K + row0) * K + jb;

    #pragma unroll
    for (int r = 0; r < ROWS; r++) {
        const float inv = inv_s[r];
        const float4 res = make_float4(v0[r] * inv, v1[r] * inv,
                                       v2[r] * inv, v3[r] * inv);
        __stcs(reinterpret_cast<float4*>(ob + (size_t)r * K), res);  // STG.128.CS
    }
}

extern "C" void kernel_launch(void* const* d_in, const int* in_sizes, int n_in,
                              void* d_out, int out_size)
{
    const float* coords = (const float*)d_in[0];   // [128, 1024, 3] f32
    const float* prec   = (const float*)d_in[1];   // [1] f32
    float* out          = (float*)d_out;           // [128, 1024, 1024] f32

    dim3 grid(128 * (K / ROWS));   // 16384 blocks
    adjacency_softmax_kernel<<<grid, THREADS>>>(coords, prec, out);
}

// round 9
// speedup vs baseline: 1.3943x; 1.1056x over previous
#include <cuda_runtime.h>
#include <cuda_bf16.h>

// out[b,i,j] = softmax_j( exp( exp(-||x_bi - x_bj||^2 * p) ) ), B=128, K=1024.
//
// R9 = R8 with ONE change: column coord loads vectorized.
// R8 profile: L1 60% dominated by 12x LDG.32 (48B lane stride -> ~12
// wavefronts each = ~144 wf/warp, 70% of L1 traffic). The 4 points per lane
// are 12 CONSECUTIVE floats, 16B aligned -> 3x LDG.128 (~36 wf/warp).
//  - 256 threads / 8 warps / 8 rows per block, 4 consecutive cols per lane,
//    STG.128.CS stores, grid 16384, no smem staging, deferred butterfly.

static constexpr int K = 1024;
static constexpr int THREADS = 256;
static constexpr int ROWS = 8;
static constexpr float LOG2E = 1.4426950408889634f;
static constexpr float LOG2_LOG2E = 0.5287663729448977f;  // log2(log2(e))

__device__ __forceinline__ float ex2f(float x) {
    float r;
    asm("ex2.approx.f32 %0, %1;" : "=f"(r) : "f"(x));
    return r;
}

__global__ void __launch_bounds__(THREADS, 4)
adjacency_softmax_kernel(const float* __restrict__ coords,
                         const float* __restrict__ prec,
                         float* __restrict__ out)
{
    __shared__ float wsum[ROWS][9];    // per-warp row sums (padded)
    __shared__ float inv_s[ROWS];

    const int b    = blockIdx.x >> 7;
    const int row0 = (blockIdx.x & 127) << 3;
    const int tid  = threadIdx.x;
    const int wid  = tid >> 5;
    const int lane = tid & 31;
    const int jb   = (wid << 7) + (lane << 2);   // 4 consecutive columns

    const float p  = prec[0];
    const float q  = -p * LOG2E;
    const float s2 = -2.0f * q;                  // +2*p*log2e

    const float* __restrict__ cb = coords + (size_t)b * K * 3;

    // ---- Column points: 12 consecutive floats -> 3x LDG.128 ----
    const float4* __restrict__ cb4 =
        reinterpret_cast<const float4*>(cb + (size_t)jb * 3);
    const float4 q0 = cb4[0];   // x0 y0 z0 x1
    const float4 q1 = cb4[1];   // y1 z1 x2 y2
    const float4 q2 = cb4[2];   // z2 x3 y3 z3

    float csx[4], csy[4], csz[4], cw[4];
    {
        const float x0 = q0.x, y0 = q0.y, z0 = q0.z;
        const float x1 = q0.w, y1 = q1.x, z1 = q1.y;
        const float x2 = q1.z, y2 = q1.w, z2 = q2.x;
        const float x3 = q2.y, y3 = q2.z, z3 = q2.w;
        cw[0] = fmaf(x0, x0, fmaf(y0, y0, z0 * z0)) * q + LOG2_LOG2E;
        cw[1] = fmaf(x1, x1, fmaf(y1, y1, z1 * z1)) * q + LOG2_LOG2E;
        cw[2] = fmaf(x2, x2, fmaf(y2, y2, z2 * z2)) * q + LOG2_LOG2E;
        cw[3] = fmaf(x3, x3, fmaf(y3, y3, z3 * z3)) * q + LOG2_LOG2E;
        csx[0] = x0 * s2; csy[0] = y0 * s2; csz[0] = z0 * s2;
        csx[1] = x1 * s2; csy[1] = y1 * s2; csz[1] = z1 * s2;
        csx[2] = x2 * s2; csy[2] = y2 * s2; csz[2] = z2 * s2;
        csx[3] = x3 * s2; csy[3] = y3 * s2; csz[3] = z3 * s2;
    }

    float v0[ROWS], v1[ROWS], v2[ROWS], v3[ROWS];

    #pragma unroll
    for (int r = 0; r < ROWS; r++) {
        // Row point: uniform-address LDG (L1-hit broadcast after first touch).
        const float ax = cb[(row0 + r) * 3 + 0];
        const float ay = cb[(row0 + r) * 3 + 1];
        const float az = cb[(row0 + r) * 3 + 2];
        const float aw = fmaf(ax, ax, fmaf(ay, ay, az * az)) * q;

        float t0 = aw + cw[0];
        float t1 = aw + cw[1];
        float t2 = aw + cw[2];
        float t3 = aw + cw[3];
        t0 = fmaf(ax, csx[0], t0);
        t1 = fmaf(ax, csx[1], t1);
        t2 = fmaf(ax, csx[2], t2);
        t3 = fmaf(ax, csx[3], t3);
        t0 = fmaf(ay, csy[0], t0);
        t1 = fmaf(ay, csy[1], t1);
        t2 = fmaf(ay, csy[2], t2);
        t3 = fmaf(ay, csy[3], t3);
        t0 = fmaf(az, csz[0], t0);
        t1 = fmaf(az, csz[1], t1);
        t2 = fmaf(az, csz[2], t2);
        t3 = fmaf(az, csz[3], t3);

        v0[r] = ex2f(ex2f(t0));                  // exp(exp(-d*p))
        v1[r] = ex2f(ex2f(t1));
        v2[r] = ex2f(ex2f(t2));
        v3[r] = ex2f(ex2f(t3));
    }

    // ---- Deferred cross-lane reduction: array-halving butterfly ----
    float s[ROWS];
    #pragma unroll
    for (int r = 0; r < ROWS; r++)
        s[r] = (v0[r] + v1[r]) + (v2[r] + v3[r]);

    #pragma unroll
    for (int stage = 0; stage < 3; stage++) {
        const int m = 1 << stage;        // xor mask: 1, 2, 4
        const int h = 4 >> stage;        // surviving half-size: 4, 2, 1
        const bool up = (lane & m) != 0;
        #pragma unroll
        for (int r = 0; r < h; r++) {
            const float x = up ? s[r + h] : s[r];
            const float y = up ? s[r]     : s[r + h];
            s[r] = x + __shfl_xor_sync(0xFFFFFFFFu, y, m);
        }
    }
    {
        float t = s[0];
        t += __shfl_xor_sync(0xFFFFFFFFu, t, 8);
        t += __shfl_xor_sync(0xFFFFFFFFu, t, 16);
        if (lane < 8) {
            const int row = ((lane & 1) << 2) | (lane & 2) | ((lane & 4) >> 2);
            wsum[row][wid] = t;
        }
    }
    __syncthreads();

    if (tid < ROWS) {
        float acc = 0.0f;
        #pragma unroll
        for (int w = 0; w < 8; w++) acc += wsum[tid][w];
        inv_s[tid] = __fdividef(1.0f, acc);
    }
    __syncthreads();

    float* __restrict__ ob = out + ((size_t)b * K + row0) * K + jb;

    #pragma unroll
    for (int r = 0; r < ROWS; r++) {
        const float inv = inv_s[r];
        const float4 res = make_float4(v0[r] * inv, v1[r] * inv,
                                       v2[r] * inv, v3[r] * inv);
        __stcs(reinterpret_cast<float4*>(ob + (size_t)r * K), res);  // STG.128.CS
    }
}

extern "C" void kernel_launch(void* const* d_in, const int* in_sizes, int n_in,
                              void* d_out, int out_size)
{
    const float* coords = (const float*)d_in[0];   // [128, 1024, 3] f32
    const float* prec   = (const float*)d_in[1];   // [1] f32
    float* out          = (float*)d_out;           // [128, 1024, 1024] f32

    dim3 grid(128 * (K / ROWS));   // 16384 blocks
    adjacency_softmax_kernel<<<grid, THREADS>>>(coords, prec, out);
}

// round 10
// speedup vs baseline: 1.4277x; 1.0240x over previous
#include <cuda_runtime.h>
#include <cuda_bf16.h>

// out[b,i,j] = softmax_j( exp( exp(-||x_bi - x_bj||^2 * p) ) ), B=128, K=1024.
//
// R10: two-phase. R9 was 3-way balanced at ~60% (DRAM / MUFU / L1); the only
// reducible term was L1, dominated by 48B-stride column gathers (36 wf/warp).
//  - Kernel A (~131K threads, one-off): expand coords into SoA scratch:
//      column side: cx=x*s2, cy, cz, cw=norm*q+log2(log2e)   (prescaled)
//      row side:    rx=x, ry, rz, rw=norm*q                   (raw)
//  - Kernel B: column loads = 4x LDG.128 at 16B lane stride (4 wf each,
//    16 wf total, was 36); row data = uniform LDG.128 (8 wf, was 24).
//    ~68 wf/warp total -> L1 ~38%. Math per element: 1 add + 3 fma + 2 EX2.
//  - Same structure as R9 otherwise: 256 thr / 8 warps / 8 rows, 4 cols/lane,
//    deferred butterfly (9 SHFL), STG.128.CS, grid 16384.

static constexpr int K = 1024;
static constexpr int B = 128;
static constexpr int BK = B * K;          // 131072 points
static constexpr int THREADS = 256;
static constexpr int ROWS = 8;
static constexpr float LOG2E = 1.4426950408889634f;
static constexpr float LOG2_LOG2E = 0.5287663729448977f;  // log2(log2(e))

// 8 x 512KB = 4MB scratch (static device arrays; no dynamic alloc).
__device__ __align__(16) float g_cx[BK];
__device__ __align__(16) float g_cy[BK];
__device__ __align__(16) float g_cz[BK];
__device__ __align__(16) float g_cw[BK];
__device__ __align__(16) float g_rx[BK];
__device__ __align__(16) float g_ry[BK];
__device__ __align__(16) float g_rz[BK];
__device__ __align__(16) float g_rw[BK];

__device__ __forceinline__ float ex2f(float x) {
    float r;
    asm("ex2.approx.f32 %0, %1;" : "=f"(r) : "f"(x));
    return r;
}

__global__ void __launch_bounds__(256)
prep_kernel(const float* __restrict__ coords, const float* __restrict__ prec)
{
    const int i = blockIdx.x * 256 + threadIdx.x;   // point index < BK
    const float q  = -prec[0] * LOG2E;
    const float s2 = -2.0f * q;

    const float x = coords[i * 3 + 0];
    const float y = coords[i * 3 + 1];
    const float z = coords[i * 3 + 2];
    const float nq = fmaf(x, x, fmaf(y, y, z * z)) * q;

    g_rx[i] = x;       g_ry[i] = y;       g_rz[i] = z;       g_rw[i] = nq;
    g_cx[i] = x * s2;  g_cy[i] = y * s2;  g_cz[i] = z * s2;  g_cw[i] = nq + LOG2_LOG2E;
}

__global__ void __launch_bounds__(THREADS, 4)
adjacency_softmax_kernel(float* __restrict__ out)
{
    __shared__ float wsum[ROWS][9];    // per-warp row sums (padded)
    __shared__ float inv_s[ROWS];

    const int bq   = blockIdx.x >> 7;
    const int row0 = (blockIdx.x & 127) << 3;
    const int tid  = threadIdx.x;
    const int wid  = tid >> 5;
    const int lane = tid & 31;
    const int base = bq << 10;
    const int jb   = base + (wid << 7) + (lane << 2);   // 4 consecutive columns

    // ---- Column values: perfectly coalesced LDG.128 (4 wf each) ----
    const float4 cx = *reinterpret_cast<const float4*>(g_cx + jb);
    const float4 cy = *reinterpret_cast<const float4*>(g_cy + jb);
    const float4 cz = *reinterpret_cast<const float4*>(g_cz + jb);
    const float4 cw = *reinterpret_cast<const float4*>(g_cw + jb);

    float v0[ROWS], v1[ROWS], v2[ROWS], v3[ROWS];

    #pragma unroll
    for (int rc = 0; rc < ROWS / 4; rc++) {
        // Row values for 4 rows: uniform LDG.128 (1 wf each after first touch).
        const int rb = base + row0 + rc * 4;
        float rx[4], ry[4], rz[4], rw[4];
        *reinterpret_cast<float4*>(rx) = *reinterpret_cast<const float4*>(g_rx + rb);
        *reinterpret_cast<float4*>(ry) = *reinterpret_cast<const float4*>(g_ry + rb);
        *reinterpret_cast<float4*>(rz) = *reinterpret_cast<const float4*>(g_rz + rb);
        *reinterpret_cast<float4*>(rw) = *reinterpret_cast<const float4*>(g_rw + rb);

        #pragma unroll
        for (int r = 0; r < 4; r++) {
            const int vr = rc * 4 + r;
            const float ax = rx[r], ay = ry[r], az = rz[r], aw = rw[r];

            float t0 = aw + cw.x;
            float t1 = aw + cw.y;
            float t2 = aw + cw.z;
            float t3 = aw + cw.w;
            t0 = fmaf(ax, cx.x, t0);
            t1 = fmaf(ax, cx.y, t1);
            t2 = fmaf(ax, cx.z, t2);
            t3 = fmaf(ax, cx.w, t3);
            t0 = fmaf(ay, cy.x, t0);
            t1 = fmaf(ay, cy.y, t1);
            t2 = fmaf(ay, cy.z, t2);
            t3 = fmaf(ay, cy.w, t3);
            t0 = fmaf(az, cz.x, t0);
            t1 = fmaf(az, cz.y, t1);
            t2 = fmaf(az, cz.z, t2);
            t3 = fmaf(az, cz.w, t3);

            v0[vr] = ex2f(ex2f(t0));             // exp(exp(-d*p))
            v1[vr] = ex2f(ex2f(t1));
            v2[vr] = ex2f(ex2f(t2));
            v3[vr] = ex2f(ex2f(t3));
        }
    }

    // ---- Deferred cross-lane reduction: array-halving butterfly ----
    float s[ROWS];
    #pragma unroll
    for (int r = 0; r < ROWS; r++)
        s[r] = (v0[r] + v1[r]) + (v2[r] + v3[r]);

    #pragma unroll
    for (int stage = 0; stage < 3; stage++) {
        const int m = 1 << stage;        // xor mask: 1, 2, 4
        const int h = 4 >> stage;        // surviving half-size: 4, 2, 1
        const bool up = (lane & m) != 0;
        #pragma unroll
        for (int r = 0; r < h; r++) {
            const float x = up ? s[r + h] : s[r];
            const float y = up ? s[r]     : s[r + h];
            s[r] = x + __shfl_xor_sync(0xFFFFFFFFu, y, m);
        }
    }
    {
        float t = s[0];
        t += __shfl_xor_sync(0xFFFFFFFFu, t, 8);
        t += __shfl_xor_sync(0xFFFFFFFFu, t, 16);
        if (lane < 8) {
            const int row = ((lane & 1) << 2) | (lane & 2) | ((lane & 4) >> 2);
            wsum[row][wid] = t;
        }
    }
    __syncthreads();

    if (tid < ROWS) {
        float acc = 0.0f;
        #pragma unroll
        for (int w = 0; w < 8; w++) acc += wsum[tid][w];
        inv_s[tid] = __fdividef(1.0f, acc);
    }
    __syncthreads();

    float* __restrict__ ob =
        out + ((size_t)bq * K + row0) * K + (jb - base);

    #pragma unroll
    for (int r = 0; r < ROWS; r++) {
        const float inv = inv_s[r];
        const float4 res = make_float4(v0[r] * inv, v1[r] * inv,
                                       v2[r] * inv, v3[r] * inv);
        __stcs(reinterpret_cast<float4*>(ob + (size_t)r * K), res);  // STG.128.CS
    }
}

extern "C" void kernel_launch(void* const* d_in, const int* in_sizes, int n_in,
                              void* d_out, int out_size)
{
    const float* coords = (const float*)d_in[0];   // [128, 1024, 3] f32
    const float* prec   = (const float*)d_in[1];   // [1] f32
    float* out          = (float*)d_out;           // [128, 1024, 1024] f32

    prep_kernel<<<BK / 256, 256>>>(coords, prec);
    dim3 grid(B * (K / ROWS));   // 16384 blocks
    adjacency_softmax_kernel<<<grid, THREADS>>>(out);
}